// round 5
// baseline (speedup 1.0000x reference)
#include <cuda_runtime.h>

// Problem shape (fixed for this dataset)
#define N_NODES 400000
#define K_DOWN  5
#define F_DIM   128
#define NUP     100000

// Scratch (allocation-free rule: __device__ globals)
__device__ float         g_push_f[(size_t)N_NODES * F_DIM];  // 204.8 MB
__device__ float         g_push_w[N_NODES];                  // 1.6 MB
__device__ unsigned char g_flag[N_NODES];                    // 0.4 MB

// ---------------------------------------------------------------------------
// K0: clear selection flags (400 KB, word stores)
__global__ void k_clear_flags() {
    int i = blockIdx.x * blockDim.x + threadIdx.x;
    const int n4 = N_NODES / 4;
    if (i < n4) ((unsigned int*)g_flag)[i] = 0u;
}

// K1: mark selected rows + zero their accumulators (warp per selected row)
__global__ void k_mark_zero(const int* __restrict__ sel) {
    int u = (blockIdx.x * blockDim.x + threadIdx.x) >> 5;
    if (u >= NUP) return;
    int lane = threadIdx.x & 31;
    int s = sel[u];
    if (s < 0 || s >= N_NODES) return;
    if (lane == 0) { g_flag[s] = 1; g_push_w[s] = 0.0f; }
    float4 z = make_float4(0.f, 0.f, 0.f, 0.f);
    ((float4*)(g_push_f + (size_t)s * F_DIM))[lane] = z;
}

// K2: scatter-add, warp per source node. Only contributions targeting a
// flagged (i.e., later-read) row are pushed -> live atomic set fits in L2.
__global__ void k_scatter(const float* __restrict__ feat,
                          const float* __restrict__ wdn,
                          const int*   __restrict__ nidx) {
    int n = (blockIdx.x * blockDim.x + threadIdx.x) >> 5;
    if (n >= N_NODES) return;
    int lane = threadIdx.x & 31;

    int   idxk = -1;
    float wk   = 0.0f;
    if (lane < K_DOWN) {
        idxk = nidx[n * K_DOWN + lane];
        wk   = wdn [n * K_DOWN + lane];
    }
    int act = (lane < K_DOWN && idxk >= 0 && idxk < N_NODES && g_flag[idxk]) ? 1 : 0;
    unsigned mask = __ballot_sync(0xffffffffu, act);
    if (!mask) return;

    // Coalesced: 4 floats per lane (row is 512B-aligned)
    float4 f = ((const float4*)(feat + (size_t)n * F_DIM))[lane];

    while (mask) {
        int k = __ffs(mask) - 1;
        mask &= mask - 1;
        int   dst = __shfl_sync(0xffffffffu, idxk, k);
        float w   = __shfl_sync(0xffffffffu, wk,   k);
        float4 v  = make_float4(w * f.x, w * f.y, w * f.z, w * f.w);
        // 128-bit vector atomic (sm_90+), 16B-aligned
        atomicAdd((float4*)(g_push_f + (size_t)dst * F_DIM + lane * 4), v);
        if (lane == 0) atomicAdd(&g_push_w[dst], w);
    }
}

// K3: gather selected rows, normalize, write output (warp per output row)
__global__ void k_gather(const int* __restrict__ sel, float* __restrict__ out) {
    int u = (blockIdx.x * blockDim.x + threadIdx.x) >> 5;
    if (u >= NUP) return;
    int lane = threadIdx.x & 31;
    int s = sel[u];

    float  wsum = 0.001f;
    float4 f    = make_float4(0.f, 0.f, 0.f, 0.f);
    if (s >= 0 && s < N_NODES) {
        float w = g_push_w[s];
        wsum = (w > 0.0f) ? w : 0.001f;
        f = ((const float4*)(g_push_f + (size_t)s * F_DIM))[lane];
    }
    float inv = 1.0f / wsum;
    float4 o = make_float4(f.x * inv, f.y * inv, f.z * inv, f.w * inv);
    ((float4*)(out + (size_t)u * F_DIM))[lane] = o;
}

// ---------------------------------------------------------------------------
extern "C" void kernel_launch(void* const* d_in, const int* in_sizes, int n_in,
                              void* d_out, int out_size) {
    const float* feat = (const float*)d_in[0];   // (N, 128) f32
    const float* wdn  = (const float*)d_in[1];   // (N, 5)   f32
    const int*   nidx = (const int*)  d_in[2];   // (N, 5)   i32
    const int*   sel  = (const int*)  d_in[3];   // (NUP, 1) i32
    float* out = (float*)d_out;                  // (NUP, 128) f32

    const int TPB = 256;

    // K0: clear flags
    {
        int n4 = N_NODES / 4;
        k_clear_flags<<<(n4 + TPB - 1) / TPB, TPB>>>();
    }
    // K1: mark + zero selected rows (warp per row)
    {
        long long thr = (long long)NUP * 32;
        k_mark_zero<<<(int)((thr + TPB - 1) / TPB), TPB>>>(sel);
    }
    // K2: scatter (warp per node)
    {
        long long thr = (long long)N_NODES * 32;
        k_scatter<<<(int)((thr + TPB - 1) / TPB), TPB>>>(feat, wdn, nidx);
    }
    // K3: gather + normalize (warp per output row)
    {
        long long thr = (long long)NUP * 32;
        k_gather<<<(int)((thr + TPB - 1) / TPB), TPB>>>(sel, out);
    }
}

// round 7
// speedup vs baseline: 1.0003x; 1.0003x over previous
#include <cuda_runtime.h>

// Problem shape (fixed for this dataset)
#define N_NODES 400000
#define K_DOWN  5
#define NCONTRIB (N_NODES * K_DOWN)   // 2,000,000
#define F_DIM   128
#define NUP     100000
#define CAP     40                    // bucket capacity per destination

// Scratch (allocation-free rule: __device__ globals)
// entry = (w:f32 << 32) | src:u32 ; 400k * 40 * 8B = 128 MB
__device__ unsigned long long g_ent[(size_t)N_NODES * CAP];
__device__ int                g_cnt[N_NODES];

// ---------------------------------------------------------------------------
// K0: zero per-destination counters (1.6 MB)
__global__ void k_clear_cnt() {
    int i = blockIdx.x * blockDim.x + threadIdx.x;
    const int n4 = N_NODES / 4;
    if (i < n4) ((int4*)g_cnt)[i] = make_int4(0, 0, 0, 0);
}

// K1: bucket fill — thread per (n,k) contribution.
__global__ void k_fill(const float* __restrict__ wdn,
                       const int*   __restrict__ nidx) {
    int t = blockIdx.x * blockDim.x + threadIdx.x;
    if (t >= NCONTRIB) return;
    int dst = nidx[t];
    if (dst < 0 || dst >= N_NODES) return;
    float w  = wdn[t];
    int src  = t / K_DOWN;
    int pos  = atomicAdd(&g_cnt[dst], 1);
    if (pos < CAP) {
        unsigned long long e =
            ((unsigned long long)__float_as_uint(w) << 32) | (unsigned int)src;
        g_ent[(size_t)dst * CAP + pos] = e;
    }
}

// K2: fused gather + normalize — warp per output row.
// Reads the bucket for sel[u], accumulates w * feat[src] in registers,
// divides by wsum (relu + 0.001 fallback), writes output. No atomics,
// no intermediate 'pushed' array.
__global__ void k_gather_fused(const int*   __restrict__ sel,
                               const float* __restrict__ feat,
                               float*       __restrict__ out) {
    int u = (blockIdx.x * blockDim.x + threadIdx.x) >> 5;
    if (u >= NUP) return;
    int lane = threadIdx.x & 31;

    int s = sel[u];
    float  wsum = 0.0f;
    float4 acc  = make_float4(0.f, 0.f, 0.f, 0.f);

    if (s >= 0 && s < N_NODES) {
        int c = g_cnt[s];
        if (c > CAP) c = CAP;
        const unsigned long long* bucket = g_ent + (size_t)s * CAP;
        const float4* feat4 = (const float4*)feat;

        for (int base = 0; base < c; base += 32) {
            int m = c - base; if (m > 32) m = 32;
            unsigned long long ev =
                (lane < m) ? bucket[base + lane] : 0ull;
            #pragma unroll 4
            for (int j = 0; j < m; j++) {
                unsigned long long e = __shfl_sync(0xffffffffu, ev, j);
                int   src = (int)(e & 0xffffffffull);
                float w   = __uint_as_float((unsigned int)(e >> 32));
                wsum += w;
                float4 f = feat4[(size_t)src * (F_DIM / 4) + lane];
                acc.x = fmaf(w, f.x, acc.x);
                acc.y = fmaf(w, f.y, acc.y);
                acc.z = fmaf(w, f.z, acc.z);
                acc.w = fmaf(w, f.w, acc.w);
            }
        }
    }

    // relu(wsum) then fallback to 0.001 when <= 0
    float ws  = (wsum > 0.0f) ? wsum : 0.001f;
    float inv = 1.0f / ws;
    float4 o  = make_float4(acc.x * inv, acc.y * inv, acc.z * inv, acc.w * inv);
    ((float4*)(out + (size_t)u * F_DIM))[lane] = o;
}

// ---------------------------------------------------------------------------
extern "C" void kernel_launch(void* const* d_in, const int* in_sizes, int n_in,
                              void* d_out, int out_size) {
    const float* feat = (const float*)d_in[0];   // (N, 128) f32
    const float* wdn  = (const float*)d_in[1];   // (N, 5)   f32
    const int*   nidx = (const int*)  d_in[2];   // (N, 5)   i32
    const int*   sel  = (const int*)  d_in[3];   // (NUP, 1) i32
    float* out = (float*)d_out;                  // (NUP, 128) f32

    const int TPB = 256;

    // K0: zero counters
    {
        int n4 = N_NODES / 4;
        k_clear_cnt<<<(n4 + TPB - 1) / TPB, TPB>>>();
    }
    // K1: bucket fill (thread per contribution)
    k_fill<<<(NCONTRIB + TPB - 1) / TPB, TPB>>>(wdn, nidx);

    // K2: fused gather + normalize (warp per output row)
    {
        long long thr = (long long)NUP * 32;
        k_gather_fused<<<(int)((thr + TPB - 1) / TPB), TPB>>>(sel, feat, out);
    }
}